// round 15
// baseline (speedup 1.0000x reference)
#include <cuda_runtime.h>
#include <cuda_bf16.h>
#include <cuda_fp16.h>
#include <cstdint>
#include <cstddef>

#define DDIM 128
#define MAXN 50000
#define MAXE 400000

// ---------------------------------------------------------------------------
// Scratch (static device globals — allocation-free rule).
// qpack[n]: [q_alpha(128) | q_beta(128)] fp16      (512 B/node)
// kpack[n]: [k_alpha | k_beta | msg_t | msg_x] fp16 (1 KB/node)
// ---------------------------------------------------------------------------
__device__ __align__(16) __half g_qpack[(size_t)MAXN * 256];
__device__ __align__(16) __half g_kpack[(size_t)MAXN * 512];
__device__ int g_deg[MAXN];
__device__ int g_roff[MAXN + 1];
__device__ int g_cur[MAXN];
__device__ int2 g_epair[MAXE];     // CSR slot -> (src, dst)
__device__ float2 g_esc[MAXE];     // CSR slot -> (e_alpha, e_beta)

constexpr int PITCH = 136;             // bf16/row (272B ≡ 16 mod 128 → conflict-free)
constexpr int ROWB  = PITCH * 2;       // 272 bytes
constexpr int TILEB = 128 * ROWB;      // 34816 B per hi-or-lo tile

constexpr int SM_AHI = 0;
constexpr int SM_ALO = SM_AHI + TILEB;          // 34816
constexpr int SM_WF  = SM_ALO + TILEB;          // 69632 (fp32 weight staging, 64KB)
constexpr int SM_WHI = SM_WF + 65536;           // 135168
constexpr int SM_WLO = SM_WHI + TILEB;          // 169984
constexpr int GEMM_SMEM = SM_WLO + TILEB;       // 204800 B

// ---------------------------------------------------------------------------
__device__ __forceinline__ uint32_t smem_u32(const void* p) {
    uint32_t a;
    asm("{ .reg .u64 t; cvta.to.shared.u64 t, %1; cvt.u32.u64 %0, t; }" : "=r"(a) : "l"(p));
    return a;
}

__device__ __forceinline__ void mma16816(float* c, const uint32_t* a,
                                         uint32_t b0, uint32_t b1) {
    asm volatile(
        "mma.sync.aligned.m16n8k16.row.col.f32.bf16.bf16.f32 "
        "{%0,%1,%2,%3}, {%4,%5,%6,%7}, {%8,%9}, {%0,%1,%2,%3};"
        : "+f"(c[0]), "+f"(c[1]), "+f"(c[2]), "+f"(c[3])
        : "r"(a[0]), "r"(a[1]), "r"(a[2]), "r"(a[3]), "r"(b0), "r"(b1));
}

__device__ __forceinline__ uint32_t pack_bf16x2(float a, float b) {
    __nv_bfloat162 t = __floats2bfloat162_rn(a, b);
    return *reinterpret_cast<uint32_t*>(&t);
}

__device__ __forceinline__ void split4(const float4& v, uint2& hi, uint2& lo) {
    float f[4] = {v.x, v.y, v.z, v.w};
    float h[4], l[4];
    #pragma unroll
    for (int j = 0; j < 4; j++) {
        h[j] = __bfloat162float(__float2bfloat16(f[j]));
        l[j] = f[j] - h[j];
    }
    hi = make_uint2(pack_bf16x2(h[0], h[1]), pack_bf16x2(h[2], h[3]));
    lo = make_uint2(pack_bf16x2(l[0], l[1]), pack_bf16x2(l[2], l[3]));
}

// cp.async 64KB fp32 weight into smem staging buffer; commits a group.
__device__ __forceinline__ void cp_w32(uint32_t sdst, const float* W) {
    const char* g = (const char*)W;
    for (int i = threadIdx.x; i < 65536 / 16; i += 256) {
        asm volatile("cp.async.cg.shared.global [%0], [%1], 16;"
                     :: "r"(sdst + i * 16), "l"(g + (size_t)i * 16) : "memory");
    }
    asm volatile("cp.async.commit_group;" ::: "memory");
}

// ---------------------------------------------------------------------------
// Split-bf16 HMMA GEMM with in-kernel weight split.
// One CTA = 128 rows, 3 projections -> packed fp16.
// by=0 (src=t): Qa -> qpack+0,  Ka -> kpack+0,   Wt·t -> kpack+256
// by=1 (src=x): Qb -> qpack+128, Kb -> kpack+128, Wx·x -> kpack+384
// ---------------------------------------------------------------------------
__global__ __launch_bounds__(256, 1)
void gemm3_kernel(const float* __restrict__ t_in, const float* __restrict__ x_in,
                  const float* __restrict__ W0a, const float* __restrict__ W1a,
                  const float* __restrict__ W2a, const float* __restrict__ W0b,
                  const float* __restrict__ W1b, const float* __restrict__ W2b,
                  const float* __restrict__ Qa_b, const float* __restrict__ Ka_b,
                  const float* __restrict__ Qb_b, const float* __restrict__ Kb_b,
                  int N)
{
    extern __shared__ char sh[];
    const uint32_t sb = smem_u32(sh);
    const int tid  = threadIdx.x;
    const int wid  = tid >> 5;
    const int lane = tid & 31;
    const int by   = blockIdx.y;
    const int row0 = blockIdx.x * 128;
    const float* src = by ? x_in : t_in;
    const float* Wp[3];
    if (by) { Wp[0] = W0b; Wp[1] = W1b; Wp[2] = W2b; }
    else    { Wp[0] = W0a; Wp[1] = W1a; Wp[2] = W2a; }

    cp_w32(sb + SM_WF, Wp[0]);

    // Convert A tile fp32 -> (hi, lo) bf16, pitch-136. Zero-pad past N.
    for (int i = tid; i < 128 * 32; i += 256) {
        int r = i >> 5, c4 = (i & 31) << 2;
        int gr = row0 + r;
        float4 v = make_float4(0.f, 0.f, 0.f, 0.f);
        if (gr < N) v = ((const float4*)(src + (size_t)gr * DDIM))[i & 31];
        uint2 h, l;
        split4(v, h, l);
        int off = r * ROWB + c4 * 2;
        *(uint2*)(sh + SM_AHI + off) = h;
        *(uint2*)(sh + SM_ALO + off) = l;
    }
    asm volatile("cp.async.wait_group 0;" ::: "memory");
    __syncthreads();

    const int g  = lane >> 2;
    const int tq = lane & 3;
    const int wr0 = (wid & 3) * 32;
    const int wc0 = (wid >> 2) * 64;

    #pragma unroll
    for (int w = 0; w < 3; w++) {
        // Split staged fp32 weight into hi/lo pitched smem tiles.
        for (int i = tid; i < 128 * 32; i += 256) {
            int r = i >> 5, c4 = (i & 31) << 2;
            float4 v = *(const float4*)(sh + SM_WF + (r * 128 + c4) * 4);
            uint2 h, l;
            split4(v, h, l);
            int off = r * ROWB + c4 * 2;
            *(uint2*)(sh + SM_WHI + off) = h;
            *(uint2*)(sh + SM_WLO + off) = l;
        }
        __syncthreads();
        if (w < 2) cp_w32(sb + SM_WF, Wp[w + 1]);   // staging free after convert

        float acc[2][8][4] = {};

        #pragma unroll
        for (int kc = 0; kc < 8; kc++) {
            const int kb = kc * 32 + tq * 4;
            uint32_t ah[2][4], al[2][4];
            #pragma unroll
            for (int mt = 0; mt < 2; mt++) {
                int rb = (wr0 + mt * 16 + g) * ROWB + kb;
                ah[mt][0] = *(const uint32_t*)(sh + SM_AHI + rb);
                ah[mt][1] = *(const uint32_t*)(sh + SM_AHI + rb + 8 * ROWB);
                ah[mt][2] = *(const uint32_t*)(sh + SM_AHI + rb + 16);
                ah[mt][3] = *(const uint32_t*)(sh + SM_AHI + rb + 8 * ROWB + 16);
                al[mt][0] = *(const uint32_t*)(sh + SM_ALO + rb);
                al[mt][1] = *(const uint32_t*)(sh + SM_ALO + rb + 8 * ROWB);
                al[mt][2] = *(const uint32_t*)(sh + SM_ALO + rb + 16);
                al[mt][3] = *(const uint32_t*)(sh + SM_ALO + rb + 8 * ROWB + 16);
            }
            #pragma unroll
            for (int nt = 0; nt < 8; nt++) {
                int bb = (wc0 + nt * 8 + g) * ROWB + kb;
                uint32_t bh0 = *(const uint32_t*)(sh + SM_WHI + bb);
                uint32_t bh1 = *(const uint32_t*)(sh + SM_WHI + bb + 16);
                uint32_t bl0 = *(const uint32_t*)(sh + SM_WLO + bb);
                uint32_t bl1 = *(const uint32_t*)(sh + SM_WLO + bb + 16);
                #pragma unroll
                for (int mt = 0; mt < 2; mt++) {
                    mma16816(acc[mt][nt], ah[mt], bh0, bh1);
                    mma16816(acc[mt][nt], ah[mt], bl0, bl1);
                    mma16816(acc[mt][nt], al[mt], bh0, bh1);
                }
            }
        }

        const float* bias = (w == 0) ? (by ? Qb_b : Qa_b)
                          : (w == 1) ? (by ? Kb_b : Ka_b) : nullptr;
        __half* out; size_t stride;
        if (w == 0)      { out = g_qpack + (by ? 128 : 0);       stride = 256; }
        else if (w == 1) { out = g_kpack + (by ? 128 : 0);       stride = 512; }
        else             { out = g_kpack + 256 + (by ? 128 : 0); stride = 512; }

        #pragma unroll
        for (int nt = 0; nt < 8; nt++) {
            const int col = wc0 + nt * 8 + 2 * tq;
            float2 bv = make_float2(0.f, 0.f);
            if (bias) bv = *(const float2*)(bias + col);
            #pragma unroll
            for (int mt = 0; mt < 2; mt++) {
                int r1 = row0 + wr0 + mt * 16 + g;
                int r2 = r1 + 8;
                if (r1 < N)
                    *(__half2*)(out + (size_t)r1 * stride + col) =
                        __floats2half2_rn(acc[mt][nt][0] + bv.x, acc[mt][nt][1] + bv.y);
                if (r2 < N)
                    *(__half2*)(out + (size_t)r2 * stride + col) =
                        __floats2half2_rn(acc[mt][nt][2] + bv.x, acc[mt][nt][3] + bv.y);
            }
        }

        if (w < 2) {
            asm volatile("cp.async.wait_group 0;" ::: "memory");
            __syncthreads();   // Wf32 staged; all warps past MMA reads of WHI/WLO
        }
    }
}

// ---------------------------------------------------------------------------
// CSR build: histogram -> 4-per-thread single-block scan -> slot scatter.
// ---------------------------------------------------------------------------
__global__ __launch_bounds__(256)
void hist_kernel(const int* __restrict__ erow, int E)
{
    int e = blockIdx.x * blockDim.x + threadIdx.x;
    if (e < E) atomicAdd(&g_deg[erow[e]], 1);
}

__global__ __launch_bounds__(1024, 1)
void scan_kernel(int N)
{
    __shared__ int wsum[32];
    __shared__ int carry_s, ctot;
    const int tid = threadIdx.x, lane = tid & 31, wid = tid >> 5;
    if (tid == 0) carry_s = 0;
    __syncthreads();

    for (int base = 0; base < N; base += 4096) {
        int i0 = base + tid * 4;
        int d[4];
        #pragma unroll
        for (int j = 0; j < 4; j++) d[j] = (i0 + j < N) ? g_deg[i0 + j] : 0;
        int s = d[0] + d[1] + d[2] + d[3];
        int inc = s;
        #pragma unroll
        for (int o = 1; o < 32; o <<= 1) {
            int u = __shfl_up_sync(0xFFFFFFFFu, inc, o);
            if (lane >= o) inc += u;
        }
        if (lane == 31) wsum[wid] = inc;
        __syncthreads();
        if (wid == 0) {
            int t0 = wsum[lane];
            int is = t0;
            #pragma unroll
            for (int o = 1; o < 32; o <<= 1) {
                int u = __shfl_up_sync(0xFFFFFFFFu, is, o);
                if (lane >= o) is += u;
            }
            wsum[lane] = is - t0;
            if (lane == 31) ctot = is;
        }
        __syncthreads();
        int excl = carry_s + wsum[wid] + inc - s;
        #pragma unroll
        for (int j = 0; j < 4; j++) {
            if (i0 + j < N) { g_roff[i0 + j] = excl; g_cur[i0 + j] = excl; }
            excl += d[j];
        }
        __syncthreads();
        if (tid == 0) carry_s += ctot;
        __syncthreads();
    }
    if (tid == 0) g_roff[N] = carry_s;
}

__global__ __launch_bounds__(256)
void scatter_kernel(const int* __restrict__ erow, const int* __restrict__ ecol, int E)
{
    int e = blockIdx.x * blockDim.x + threadIdx.x;
    if (e >= E) return;
    int r = erow[e];
    int slot = atomicAdd(&g_cur[r], 1);
    g_epair[slot] = make_int2(ecol[e], r);
}

// ---------------------------------------------------------------------------
// Pass A: per-edge scores. One warp per CSR slot, no loop-carried deps.
// ---------------------------------------------------------------------------
__global__ __launch_bounds__(256)
void score_kernel(int E)
{
    const int s    = (blockIdx.x * blockDim.x + threadIdx.x) >> 5;
    const int lane = threadIdx.x & 31;
    if (s >= E) return;

    const int2 pr = g_epair[s];
    const int c = pr.x, r = pr.y;
    const int l4 = lane * 4;

    uint2 qa = *(const uint2*)(g_qpack + (size_t)r * 256 + l4);
    uint2 qb = *(const uint2*)(g_qpack + (size_t)r * 256 + 128 + l4);
    uint2 ka = *(const uint2*)(g_kpack + (size_t)c * 512 + l4);
    uint2 kb = *(const uint2*)(g_kpack + (size_t)c * 512 + 128 + l4);

    float2 a0 = __half22float2(*(__half2*)&qa.x), a1 = __half22float2(*(__half2*)&qa.y);
    float2 b0 = __half22float2(*(__half2*)&ka.x), b1 = __half22float2(*(__half2*)&ka.y);
    float sa = a0.x * b0.x + a0.y * b0.y + a1.x * b1.x + a1.y * b1.y;
    a0 = __half22float2(*(__half2*)&qb.x); a1 = __half22float2(*(__half2*)&qb.y);
    b0 = __half22float2(*(__half2*)&kb.x); b1 = __half22float2(*(__half2*)&kb.y);
    float sb = a0.x * b0.x + a0.y * b0.y + a1.x * b1.x + a1.y * b1.y;

    #pragma unroll
    for (int off = 16; off; off >>= 1) {
        sa += __shfl_xor_sync(0xFFFFFFFFu, sa, off);
        sb += __shfl_xor_sync(0xFFFFFFFFu, sb, off);
    }

    const float inv_sqrt_d = 0.08838834764831845f;   // 1/sqrt(128)
    if (lane == 0)
        g_esc[s] = make_float2(__expf(sa * inv_sqrt_d), __expf(sb * inv_sqrt_d));
}

// ---------------------------------------------------------------------------
// Pass B: warp per node. Sequential score reads + msg gathers; loop-carried
// dependency is a single FMA. Normalized single store.
// ---------------------------------------------------------------------------
__global__ __launch_bounds__(256)
void gather_kernel(float* __restrict__ out_x, float* __restrict__ out_t, int N)
{
    const int n    = (blockIdx.x * blockDim.x + threadIdx.x) >> 5;
    const int lane = threadIdx.x & 31;
    if (n >= N) return;

    const int l4 = lane * 4;
    const int start = g_roff[n], end = g_roff[n + 1];

    float4 acct = make_float4(0.f, 0.f, 0.f, 0.f);
    float4 accx = make_float4(0.f, 0.f, 0.f, 0.f);
    float dena = 0.f, denb = 0.f;

    #pragma unroll 2
    for (int i = start; i < end; i++) {
        const int c = g_epair[i].x;
        const float2 esc = g_esc[i];
        const __half* kp = g_kpack + (size_t)c * 512 + 256;
        uint2 mt = *(const uint2*)(kp + l4);
        uint2 mx = *(const uint2*)(kp + 128 + l4);

        dena += esc.x; denb += esc.y;

        float2 v0 = __half22float2(*(__half2*)&mt.x), v1 = __half22float2(*(__half2*)&mt.y);
        acct.x = fmaf(esc.x, v0.x, acct.x); acct.y = fmaf(esc.x, v0.y, acct.y);
        acct.z = fmaf(esc.x, v1.x, acct.z); acct.w = fmaf(esc.x, v1.y, acct.w);
        v0 = __half22float2(*(__half2*)&mx.x); v1 = __half22float2(*(__half2*)&mx.y);
        accx.x = fmaf(esc.y, v0.x, accx.x); accx.y = fmaf(esc.y, v0.y, accx.y);
        accx.z = fmaf(esc.y, v1.x, accx.z); accx.w = fmaf(esc.y, v1.y, accx.w);
    }

    float ra = dena > 0.f ? __fdividef(1.f, dena) : 0.f;
    float rb = denb > 0.f ? __fdividef(1.f, denb) : 0.f;
    acct.x *= ra; acct.y *= ra; acct.z *= ra; acct.w *= ra;
    accx.x *= rb; accx.y *= rb; accx.z *= rb; accx.w *= rb;

    *(float4*)(out_t + (size_t)n * DDIM + l4) = acct;
    *(float4*)(out_x + (size_t)n * DDIM + l4) = accx;
}

// ---------------------------------------------------------------------------
extern "C" void kernel_launch(void* const* d_in, const int* in_sizes, int n_in,
                              void* d_out, int out_size)
{
    const float* x    = (const float*)d_in[0];
    const float* t    = (const float*)d_in[1];
    const int*   ei   = (const int*)d_in[2];
    const float* W_x  = (const float*)d_in[3];
    const float* W_t  = (const float*)d_in[4];
    const float* Qa_w = (const float*)d_in[5];
    const float* Qa_b = (const float*)d_in[6];
    const float* Ka_w = (const float*)d_in[7];
    const float* Ka_b = (const float*)d_in[8];
    const float* Qb_w = (const float*)d_in[9];
    const float* Qb_b = (const float*)d_in[10];
    const float* Kb_w = (const float*)d_in[11];
    const float* Kb_b = (const float*)d_in[12];

    const int N = in_sizes[0] / DDIM;
    const int E = in_sizes[2] / 2;
    const int* erow = ei;         // edge_index[0] = dest
    const int* ecol = ei + E;     // edge_index[1] = src

    float* out_x = (float*)d_out;
    float* out_t = out_x + (size_t)N * DDIM;

    int* deg = nullptr;
    cudaGetSymbolAddress((void**)&deg, g_deg);
    cudaMemsetAsync(deg, 0, sizeof(int) * N, 0);

    // CSR build
    const int eb = (E + 255) / 256;
    hist_kernel<<<eb, 256>>>(erow, E);
    scan_kernel<<<1, 1024>>>(N);
    scatter_kernel<<<eb, 256>>>(erow, ecol, E);

    // Projections (weight split folded in)
    cudaFuncSetAttribute(gemm3_kernel,
                         cudaFuncAttributeMaxDynamicSharedMemorySize, GEMM_SMEM);
    dim3 gg((N + 127) / 128, 2);
    gemm3_kernel<<<gg, 256, GEMM_SMEM>>>(t, x,
                                         Qa_w, Ka_w, W_t, Qb_w, Kb_w, W_x,
                                         Qa_b, Ka_b, Qb_b, Kb_b, N);

    // Pass A: per-edge scores (warp per CSR slot)
    const int sb = (E * 32 + 255) / 256;
    score_kernel<<<sb, 256>>>(E);

    // Pass B: per-node gather + normalize + store
    const int nb = (N * 32 + 255) / 256;
    gather_kernel<<<nb, 256>>>(out_x, out_t, N);
}

// round 16
// speedup vs baseline: 1.1869x; 1.1869x over previous
#include <cuda_runtime.h>
#include <cuda_bf16.h>
#include <cuda_fp16.h>
#include <cstdint>
#include <cstddef>

#define DDIM 128
#define MAXN 50000
#define MAXE 400000

// ---------------------------------------------------------------------------
// Scratch (static device globals — allocation-free rule).
// qpack[n]: [q_alpha(128) | q_beta(128)] fp16      (512 B/node)
// kpack[n]: [k_alpha | k_beta | msg_t | msg_x] fp16 (1 KB/node)
// ---------------------------------------------------------------------------
__device__ __align__(16) __half g_qpack[(size_t)MAXN * 256];
__device__ __align__(16) __half g_kpack[(size_t)MAXN * 512];
__device__ __nv_bfloat16 g_wsplit[6 * 2 * 128 * 136];   // per weight: hi|lo, pitch 136
__device__ int g_deg[MAXN];
__device__ int g_roff[MAXN + 1];
__device__ int g_cur[MAXN];
__device__ int2 g_epair[MAXE];     // CSR slot -> (src, dst)
__device__ float2 g_esc[MAXE];     // CSR slot -> (e_alpha, e_beta)

constexpr int PITCH = 136;             // bf16/row (272B ≡ 16 mod 128 → conflict-free)
constexpr int ROWB  = PITCH * 2;       // 272 bytes
constexpr int TILEB = 128 * ROWB;      // 34816 B per hi-or-lo tile
constexpr int WELEM = 2 * 128 * PITCH; // elems per weight (hi+lo)

constexpr int SM_AHI = 0;
constexpr int SM_ALO = SM_AHI + TILEB;          // 34816
constexpr int SM_WB  = SM_ALO + TILEB;          // 69632 (single half-slab W buffer)
constexpr int GEMM_SMEM = SM_WB + TILEB;        // 104448 B -> 2 CTAs/SM

// ---------------------------------------------------------------------------
__device__ __forceinline__ uint32_t smem_u32(const void* p) {
    uint32_t a;
    asm("{ .reg .u64 t; cvta.to.shared.u64 t, %1; cvt.u32.u64 %0, t; }" : "=r"(a) : "l"(p));
    return a;
}

__device__ __forceinline__ void mma16816(float* c, const uint32_t* a,
                                         uint32_t b0, uint32_t b1) {
    asm volatile(
        "mma.sync.aligned.m16n8k16.row.col.f32.bf16.bf16.f32 "
        "{%0,%1,%2,%3}, {%4,%5,%6,%7}, {%8,%9}, {%0,%1,%2,%3};"
        : "+f"(c[0]), "+f"(c[1]), "+f"(c[2]), "+f"(c[3])
        : "r"(a[0]), "r"(a[1]), "r"(a[2]), "r"(a[3]), "r"(b0), "r"(b1));
}

__device__ __forceinline__ uint32_t pack_bf16x2(float a, float b) {
    __nv_bfloat162 t = __floats2bfloat162_rn(a, b);
    return *reinterpret_cast<uint32_t*>(&t);
}

__device__ __forceinline__ void split4(const float4& v, uint2& hi, uint2& lo) {
    float f[4] = {v.x, v.y, v.z, v.w};
    float h[4], l[4];
    #pragma unroll
    for (int j = 0; j < 4; j++) {
        h[j] = __bfloat162float(__float2bfloat16(f[j]));
        l[j] = f[j] - h[j];
    }
    hi = make_uint2(pack_bf16x2(h[0], h[1]), pack_bf16x2(h[2], h[3]));
    lo = make_uint2(pack_bf16x2(l[0], l[1]), pack_bf16x2(l[2], l[3]));
}

// ---------------------------------------------------------------------------
// Weight pre-split: fp32 [128,128] -> hi/lo bf16 pitched tiles, ONCE globally.
// grid (6, 8): blockIdx.x = weight, blockIdx.y = 16-row band.
// ---------------------------------------------------------------------------
__global__ void wsplit_kernel(const float* W0, const float* W1, const float* W2,
                              const float* W3, const float* W4, const float* W5)
{
    const float* Ws[6] = {W0, W1, W2, W3, W4, W5};
    const float* W = Ws[blockIdx.x];
    char* hi = (char*)(g_wsplit + (size_t)blockIdx.x * WELEM);
    char* lo = hi + TILEB;
    const int rbase = blockIdx.y * 16;

    for (int i = threadIdx.x; i < 16 * 32; i += 256) {
        int r = rbase + (i >> 5), c4 = (i & 31) << 2;
        float4 v = ((const float4*)W)[r * 32 + (i & 31)];
        uint2 h, l;
        split4(v, h, l);
        int off = r * ROWB + c4 * 2;
        *(uint2*)(hi + off) = h;
        *(uint2*)(lo + off) = l;
    }
}

// cp.async one half-slab (34816 B) into smem; commits a group.
__device__ __forceinline__ void cp_half(uint32_t sdst, const char* g) {
    for (int i = threadIdx.x; i < TILEB / 16; i += 256) {
        asm volatile("cp.async.cg.shared.global [%0], [%1], 16;"
                     :: "r"(sdst + i * 16), "l"(g + (size_t)i * 16) : "memory");
    }
    asm volatile("cp.async.commit_group;" ::: "memory");
}
#define CP_WAIT() do { \
    asm volatile("cp.async.wait_group 0;" ::: "memory"); __syncthreads(); } while (0)

// ---------------------------------------------------------------------------
// Split-bf16 HMMA GEMM, 2 CTAs/SM. One CTA = 128 rows, 3 projections.
// W streamed per hi/lo half through a single 34KB buffer:
//   hi resident: acc += Ahi·Bhi + Alo·Bhi;  lo resident: acc += Ahi·Blo.
// by=0 (src=t): Qa -> qpack+0,  Ka -> kpack+0,   Wt·t -> kpack+256
// by=1 (src=x): Qb -> qpack+128, Kb -> kpack+128, Wx·x -> kpack+384
// ---------------------------------------------------------------------------
__global__ __launch_bounds__(256, 2)
void gemm3_kernel(const float* __restrict__ t_in, const float* __restrict__ x_in,
                  const float* __restrict__ Qa_b, const float* __restrict__ Ka_b,
                  const float* __restrict__ Qb_b, const float* __restrict__ Kb_b,
                  int N)
{
    extern __shared__ char sh[];
    const uint32_t sb = smem_u32(sh);
    const int tid  = threadIdx.x;
    const int wid  = tid >> 5;
    const int lane = tid & 31;
    const int by   = blockIdx.y;
    const int row0 = blockIdx.x * 128;
    const float* src = by ? x_in : t_in;
    const char* wbase = (const char*)(g_wsplit + (size_t)(by * 3) * WELEM);

    // Prefetch first weight's hi half while converting A.
    cp_half(sb + SM_WB, wbase);

    for (int i = tid; i < 128 * 32; i += 256) {
        int r = i >> 5, c4 = (i & 31) << 2;
        int gr = row0 + r;
        float4 v = make_float4(0.f, 0.f, 0.f, 0.f);
        if (gr < N) v = ((const float4*)(src + (size_t)gr * DDIM))[i & 31];
        uint2 h, l;
        split4(v, h, l);
        int off = r * ROWB + c4 * 2;
        *(uint2*)(sh + SM_AHI + off) = h;
        *(uint2*)(sh + SM_ALO + off) = l;
    }
    CP_WAIT();

    const int g  = lane >> 2;
    const int tq = lane & 3;
    const int wr0 = (wid & 3) * 32;
    const int wc0 = (wid >> 2) * 64;

    #pragma unroll
    for (int w = 0; w < 3; w++) {
        const char* wsl = wbase + (size_t)w * (2 * TILEB);
        if (w > 0) { cp_half(sb + SM_WB, wsl); CP_WAIT(); }   // hi half

        float acc[2][8][4] = {};

        // Phase 1: B-hi resident -> Ahi·Bhi + Alo·Bhi
        #pragma unroll
        for (int kc = 0; kc < 8; kc++) {
            const int kb = kc * 32 + tq * 4;
            uint32_t ah[2][4], al[2][4];
            #pragma unroll
            for (int mt = 0; mt < 2; mt++) {
                int rb = (wr0 + mt * 16 + g) * ROWB + kb;
                ah[mt][0] = *(const uint32_t*)(sh + SM_AHI + rb);
                ah[mt][1] = *(const uint32_t*)(sh + SM_AHI + rb + 8 * ROWB);
                ah[mt][2] = *(const uint32_t*)(sh + SM_AHI + rb + 16);
                ah[mt][3] = *(const uint32_t*)(sh + SM_AHI + rb + 8 * ROWB + 16);
                al[mt][0] = *(const uint32_t*)(sh + SM_ALO + rb);
                al[mt][1] = *(const uint32_t*)(sh + SM_ALO + rb + 8 * ROWB);
                al[mt][2] = *(const uint32_t*)(sh + SM_ALO + rb + 16);
                al[mt][3] = *(const uint32_t*)(sh + SM_ALO + rb + 8 * ROWB + 16);
            }
            #pragma unroll
            for (int nt = 0; nt < 8; nt++) {
                int bb = (wc0 + nt * 8 + g) * ROWB + kb;
                uint32_t b0 = *(const uint32_t*)(sh + SM_WB + bb);
                uint32_t b1 = *(const uint32_t*)(sh + SM_WB + bb + 16);
                #pragma unroll
                for (int mt = 0; mt < 2; mt++) {
                    mma16816(acc[mt][nt], ah[mt], b0, b1);
                    mma16816(acc[mt][nt], al[mt], b0, b1);
                }
            }
        }
        __syncthreads();                         // all warps done with hi
        cp_half(sb + SM_WB, wsl + TILEB);        // lo half
        CP_WAIT();

        // Phase 2: B-lo resident -> Ahi·Blo
        #pragma unroll
        for (int kc = 0; kc < 8; kc++) {
            const int kb = kc * 32 + tq * 4;
            uint32_t ah[2][4];
            #pragma unroll
            for (int mt = 0; mt < 2; mt++) {
                int rb = (wr0 + mt * 16 + g) * ROWB + kb;
                ah[mt][0] = *(const uint32_t*)(sh + SM_AHI + rb);
                ah[mt][1] = *(const uint32_t*)(sh + SM_AHI + rb + 8 * ROWB);
                ah[mt][2] = *(const uint32_t*)(sh + SM_AHI + rb + 16);
                ah[mt][3] = *(const uint32_t*)(sh + SM_AHI + rb + 8 * ROWB + 16);
            }
            #pragma unroll
            for (int nt = 0; nt < 8; nt++) {
                int bb = (wc0 + nt * 8 + g) * ROWB + kb;
                uint32_t b0 = *(const uint32_t*)(sh + SM_WB + bb);
                uint32_t b1 = *(const uint32_t*)(sh + SM_WB + bb + 16);
                #pragma unroll
                for (int mt = 0; mt < 2; mt++)
                    mma16816(acc[mt][nt], ah[mt], b0, b1);
            }
        }

        // Epilogue: bias + fp16 pack stores.
        const float* bias = (w == 0) ? (by ? Qb_b : Qa_b)
                          : (w == 1) ? (by ? Kb_b : Ka_b) : nullptr;
        __half* out; size_t stride;
        if (w == 0)      { out = g_qpack + (by ? 128 : 0);       stride = 256; }
        else if (w == 1) { out = g_kpack + (by ? 128 : 0);       stride = 512; }
        else             { out = g_kpack + 256 + (by ? 128 : 0); stride = 512; }

        #pragma unroll
        for (int nt = 0; nt < 8; nt++) {
            const int col = wc0 + nt * 8 + 2 * tq;
            float2 bv = make_float2(0.f, 0.f);
            if (bias) bv = *(const float2*)(bias + col);
            #pragma unroll
            for (int mt = 0; mt < 2; mt++) {
                int r1 = row0 + wr0 + mt * 16 + g;
                int r2 = r1 + 8;
                if (r1 < N)
                    *(__half2*)(out + (size_t)r1 * stride + col) =
                        __floats2half2_rn(acc[mt][nt][0] + bv.x, acc[mt][nt][1] + bv.y);
                if (r2 < N)
                    *(__half2*)(out + (size_t)r2 * stride + col) =
                        __floats2half2_rn(acc[mt][nt][2] + bv.x, acc[mt][nt][3] + bv.y);
            }
        }
        __syncthreads();   // release W buffer before next weight's cp
    }
}

// ---------------------------------------------------------------------------
// CSR build: histogram -> 4-per-thread single-block scan -> slot scatter.
// ---------------------------------------------------------------------------
__global__ __launch_bounds__(256)
void hist_kernel(const int* __restrict__ erow, int E)
{
    int e = blockIdx.x * blockDim.x + threadIdx.x;
    if (e < E) atomicAdd(&g_deg[erow[e]], 1);
}

__global__ __launch_bounds__(1024, 1)
void scan_kernel(int N)
{
    __shared__ int wsum[32];
    __shared__ int carry_s, ctot;
    const int tid = threadIdx.x, lane = tid & 31, wid = tid >> 5;
    if (tid == 0) carry_s = 0;
    __syncthreads();

    for (int base = 0; base < N; base += 4096) {
        int i0 = base + tid * 4;
        int d[4];
        #pragma unroll
        for (int j = 0; j < 4; j++) d[j] = (i0 + j < N) ? g_deg[i0 + j] : 0;
        int s = d[0] + d[1] + d[2] + d[3];
        int inc = s;
        #pragma unroll
        for (int o = 1; o < 32; o <<= 1) {
            int u = __shfl_up_sync(0xFFFFFFFFu, inc, o);
            if (lane >= o) inc += u;
        }
        if (lane == 31) wsum[wid] = inc;
        __syncthreads();
        if (wid == 0) {
            int t0 = wsum[lane];
            int is = t0;
            #pragma unroll
            for (int o = 1; o < 32; o <<= 1) {
                int u = __shfl_up_sync(0xFFFFFFFFu, is, o);
                if (lane >= o) is += u;
            }
            wsum[lane] = is - t0;
            if (lane == 31) ctot = is;
        }
        __syncthreads();
        int excl = carry_s + wsum[wid] + inc - s;
        #pragma unroll
        for (int j = 0; j < 4; j++) {
            if (i0 + j < N) { g_roff[i0 + j] = excl; g_cur[i0 + j] = excl; }
            excl += d[j];
        }
        __syncthreads();
        if (tid == 0) carry_s += ctot;
        __syncthreads();
    }
    if (tid == 0) g_roff[N] = carry_s;
}

__global__ __launch_bounds__(256)
void scatter_kernel(const int* __restrict__ erow, const int* __restrict__ ecol, int E)
{
    int e = blockIdx.x * blockDim.x + threadIdx.x;
    if (e >= E) return;
    int r = erow[e];
    int slot = atomicAdd(&g_cur[r], 1);
    g_epair[slot] = make_int2(ecol[e], r);
}

// ---------------------------------------------------------------------------
// Pass A: per-edge scores. One warp per CSR slot (dst-sorted -> q reads cached).
// ---------------------------------------------------------------------------
__global__ __launch_bounds__(256)
void score_kernel(int E)
{
    const int s    = (blockIdx.x * blockDim.x + threadIdx.x) >> 5;
    const int lane = threadIdx.x & 31;
    if (s >= E) return;

    const int2 pr = g_epair[s];
    const int c = pr.x, r = pr.y;
    const int l4 = lane * 4;

    uint2 qa = *(const uint2*)(g_qpack + (size_t)r * 256 + l4);
    uint2 qb = *(const uint2*)(g_qpack + (size_t)r * 256 + 128 + l4);
    uint2 ka = *(const uint2*)(g_kpack + (size_t)c * 512 + l4);
    uint2 kb = *(const uint2*)(g_kpack + (size_t)c * 512 + 128 + l4);

    float2 a0 = __half22float2(*(__half2*)&qa.x), a1 = __half22float2(*(__half2*)&qa.y);
    float2 b0 = __half22float2(*(__half2*)&ka.x), b1 = __half22float2(*(__half2*)&ka.y);
    float sa = a0.x * b0.x + a0.y * b0.y + a1.x * b1.x + a1.y * b1.y;
    a0 = __half22float2(*(__half2*)&qb.x); a1 = __half22float2(*(__half2*)&qb.y);
    b0 = __half22float2(*(__half2*)&kb.x); b1 = __half22float2(*(__half2*)&kb.y);
    float sb = a0.x * b0.x + a0.y * b0.y + a1.x * b1.x + a1.y * b1.y;

    #pragma unroll
    for (int off = 16; off; off >>= 1) {
        sa += __shfl_xor_sync(0xFFFFFFFFu, sa, off);
        sb += __shfl_xor_sync(0xFFFFFFFFu, sb, off);
    }

    const float inv_sqrt_d = 0.08838834764831845f;   // 1/sqrt(128)
    if (lane == 0)
        g_esc[s] = make_float2(__expf(sa * inv_sqrt_d), __expf(sb * inv_sqrt_d));
}

// ---------------------------------------------------------------------------
// Pass B: warp per node. Sequential score reads + msg gathers; loop-carried
// dependency is a single FMA. Normalized single store.
// ---------------------------------------------------------------------------
__global__ __launch_bounds__(256)
void gather_kernel(float* __restrict__ out_x, float* __restrict__ out_t, int N)
{
    const int n    = (blockIdx.x * blockDim.x + threadIdx.x) >> 5;
    const int lane = threadIdx.x & 31;
    if (n >= N) return;

    const int l4 = lane * 4;
    const int start = g_roff[n], end = g_roff[n + 1];

    float4 acct = make_float4(0.f, 0.f, 0.f, 0.f);
    float4 accx = make_float4(0.f, 0.f, 0.f, 0.f);
    float dena = 0.f, denb = 0.f;

    #pragma unroll 2
    for (int i = start; i < end; i++) {
        const int c = g_epair[i].x;
        const float2 esc = g_esc[i];
        const __half* kp = g_kpack + (size_t)c * 512 + 256;
        uint2 mt = *(const uint2*)(kp + l4);
        uint2 mx = *(const uint2*)(kp + 128 + l4);

        dena += esc.x; denb += esc.y;

        float2 v0 = __half22float2(*(__half2*)&mt.x), v1 = __half22float2(*(__half2*)&mt.y);
        acct.x = fmaf(esc.x, v0.x, acct.x); acct.y = fmaf(esc.x, v0.y, acct.y);
        acct.z = fmaf(esc.x, v1.x, acct.z); acct.w = fmaf(esc.x, v1.y, acct.w);
        v0 = __half22float2(*(__half2*)&mx.x); v1 = __half22float2(*(__half2*)&mx.y);
        accx.x = fmaf(esc.y, v0.x, accx.x); accx.y = fmaf(esc.y, v0.y, accx.y);
        accx.z = fmaf(esc.y, v1.x, accx.z); accx.w = fmaf(esc.y, v1.y, accx.w);
    }

    float ra = dena > 0.f ? __fdividef(1.f, dena) : 0.f;
    float rb = denb > 0.f ? __fdividef(1.f, denb) : 0.f;
    acct.x *= ra; acct.y *= ra; acct.z *= ra; acct.w *= ra;
    accx.x *= rb; accx.y *= rb; accx.z *= rb; accx.w *= rb;

    *(float4*)(out_t + (size_t)n * DDIM + l4) = acct;
    *(float4*)(out_x + (size_t)n * DDIM + l4) = accx;
}

// ---------------------------------------------------------------------------
extern "C" void kernel_launch(void* const* d_in, const int* in_sizes, int n_in,
                              void* d_out, int out_size)
{
    const float* x    = (const float*)d_in[0];
    const float* t    = (const float*)d_in[1];
    const int*   ei   = (const int*)d_in[2];
    const float* W_x  = (const float*)d_in[3];
    const float* W_t  = (const float*)d_in[4];
    const float* Qa_w = (const float*)d_in[5];
    const float* Qa_b = (const float*)d_in[6];
    const float* Ka_w = (const float*)d_in[7];
    const float* Ka_b = (const float*)d_in[8];
    const float* Qb_w = (const float*)d_in[9];
    const float* Qb_b = (const float*)d_in[10];
    const float* Kb_w = (const float*)d_in[11];
    const float* Kb_b = (const float*)d_in[12];

    const int N = in_sizes[0] / DDIM;
    const int E = in_sizes[2] / 2;
    const int* erow = ei;         // edge_index[0] = dest
    const int* ecol = ei + E;     // edge_index[1] = src

    float* out_x = (float*)d_out;
    float* out_t = out_x + (size_t)N * DDIM;

    int* deg = nullptr;
    cudaGetSymbolAddress((void**)&deg, g_deg);
    cudaMemsetAsync(deg, 0, sizeof(int) * N, 0);

    // Weight pre-split (once, parallel): 0=Qa 1=Ka 2=Wt | 3=Qb 4=Kb 5=Wx
    dim3 wg(6, 8);
    wsplit_kernel<<<wg, 256>>>(Qa_w, Ka_w, W_t, Qb_w, Kb_w, W_x);

    // CSR build
    const int eb = (E + 255) / 256;
    hist_kernel<<<eb, 256>>>(erow, E);
    scan_kernel<<<1, 1024>>>(N);
    scatter_kernel<<<eb, 256>>>(erow, ecol, E);

    // Projections (2 CTAs/SM)
    cudaFuncSetAttribute(gemm3_kernel,
                         cudaFuncAttributeMaxDynamicSharedMemorySize, GEMM_SMEM);
    dim3 gg((N + 127) / 128, 2);
    gemm3_kernel<<<gg, 256, GEMM_SMEM>>>(t, x, Qa_b, Ka_b, Qb_b, Kb_b, N);

    // Pass A: per-edge scores (warp per CSR slot)
    const int sbk = (E * 32 + 255) / 256;
    score_kernel<<<sbk, 256>>>(E);

    // Pass B: per-node gather + normalize + store
    const int nb = (N * 32 + 255) / 256;
    gather_kernel<<<nb, 256>>>(out_x, out_t, N);
}

// round 17
// speedup vs baseline: 1.2731x; 1.0727x over previous
#include <cuda_runtime.h>
#include <cuda_fp16.h>
#include <cstdint>
#include <cstddef>

#define DDIM 128
#define MAXN 50000
#define MAXE 400000

// ---------------------------------------------------------------------------
// Scratch (static device globals — allocation-free rule).
// qpack[n]: [q_alpha(128) | q_beta(128)] fp16      (512 B/node)
// kpack[n]: [k_alpha | k_beta | msg_t | msg_x] fp16 (1 KB/node)
// ---------------------------------------------------------------------------
__device__ __align__(16) __half g_qpack[(size_t)MAXN * 256];
__device__ __align__(16) __half g_kpack[(size_t)MAXN * 512];
__device__ __align__(16) __half g_wh[6 * 128 * 136];    // per weight: fp16, pitch 136
__device__ int g_deg[MAXN];
__device__ int g_roff[MAXN + 1];
__device__ int g_cur[MAXN];
__device__ int g_esrc[MAXE];       // CSR slot -> src node
__device__ float2 g_esc[MAXE];     // CSR slot -> (e_alpha, e_beta)

constexpr int PITCH = 136;             // fp16/row (272B ≡ 16 mod 128 → conflict-free)
constexpr int ROWB  = PITCH * 2;       // 272 bytes
constexpr int TILEB = 128 * ROWB;      // 34816 B per tile
constexpr int WELEM = 128 * PITCH;     // fp16 elems per weight

constexpr int SM_AHI = 0;
constexpr int SM_ALO = SM_AHI + TILEB;          // 34816
constexpr int SM_WB  = SM_ALO + TILEB;          // 69632 (single fp16 W tile)
constexpr int GEMM_SMEM = SM_WB + TILEB;        // 104448 B -> 2 CTAs/SM

// ---------------------------------------------------------------------------
__device__ __forceinline__ uint32_t smem_u32(const void* p) {
    uint32_t a;
    asm("{ .reg .u64 t; cvta.to.shared.u64 t, %1; cvt.u32.u64 %0, t; }" : "=r"(a) : "l"(p));
    return a;
}

__device__ __forceinline__ void mma16816(float* c, const uint32_t* a,
                                         uint32_t b0, uint32_t b1) {
    asm volatile(
        "mma.sync.aligned.m16n8k16.row.col.f32.f16.f16.f32 "
        "{%0,%1,%2,%3}, {%4,%5,%6,%7}, {%8,%9}, {%0,%1,%2,%3};"
        : "+f"(c[0]), "+f"(c[1]), "+f"(c[2]), "+f"(c[3])
        : "r"(a[0]), "r"(a[1]), "r"(a[2]), "r"(a[3]), "r"(b0), "r"(b1));
}

__device__ __forceinline__ uint32_t pack_h2(float a, float b) {
    __half2 t = __floats2half2_rn(a, b);
    return *reinterpret_cast<uint32_t*>(&t);
}

// fp16 split: hi = fp16(x), lo = fp16(x - hi). A is O(1) so lo stays normal.
__device__ __forceinline__ void split4h(const float4& v, uint2& hi, uint2& lo) {
    float f[4] = {v.x, v.y, v.z, v.w};
    float h[4], l[4];
    #pragma unroll
    for (int j = 0; j < 4; j++) {
        h[j] = __half2float(__float2half_rn(f[j]));
        l[j] = f[j] - h[j];
    }
    hi = make_uint2(pack_h2(h[0], h[1]), pack_h2(h[2], h[3]));
    lo = make_uint2(pack_h2(l[0], l[1]), pack_h2(l[2], l[3]));
}

// ---------------------------------------------------------------------------
// Weight convert: fp32 [128,128] -> single fp16 pitched tile, once globally.
// grid (6, 8): blockIdx.x = weight, blockIdx.y = 16-row band.
// ---------------------------------------------------------------------------
__global__ void wconv_kernel(const float* W0, const float* W1, const float* W2,
                             const float* W3, const float* W4, const float* W5)
{
    const float* Ws[6] = {W0, W1, W2, W3, W4, W5};
    const float* W = Ws[blockIdx.x];
    char* dst = (char*)(g_wh + (size_t)blockIdx.x * WELEM);
    const int rbase = blockIdx.y * 16;

    for (int i = threadIdx.x; i < 16 * 32; i += 256) {
        int r = rbase + (i >> 5), c4 = (i & 31) << 2;
        float4 v = ((const float4*)W)[r * 32 + (i & 31)];
        uint2 h = make_uint2(pack_h2(v.x, v.y), pack_h2(v.z, v.w));
        *(uint2*)(dst + r * ROWB + c4 * 2) = h;
    }
}

// cp.async one tile (34816 B) into smem; commits a group.
__device__ __forceinline__ void cp_tile(uint32_t sdst, const char* g) {
    for (int i = threadIdx.x; i < TILEB / 16; i += 256) {
        asm volatile("cp.async.cg.shared.global [%0], [%1], 16;"
                     :: "r"(sdst + i * 16), "l"(g + (size_t)i * 16) : "memory");
    }
    asm volatile("cp.async.commit_group;" ::: "memory");
}
#define CP_WAIT() do { \
    asm volatile("cp.async.wait_group 0;" ::: "memory"); __syncthreads(); } while (0)

// ---------------------------------------------------------------------------
// 2-term fp16 split HMMA GEMM, 2 CTAs/SM. One CTA = 128 rows, 3 projections.
//   acc = Ahi·B + Alo·B   (B = fp16(W); B-rounding ~ the fp16 output rounding)
// by=0 (src=t): Qa -> qpack+0,  Ka -> kpack+0,   Wt·t -> kpack+256
// by=1 (src=x): Qb -> qpack+128, Kb -> kpack+128, Wx·x -> kpack+384
// ---------------------------------------------------------------------------
__global__ __launch_bounds__(256, 2)
void gemm3_kernel(const float* __restrict__ t_in, const float* __restrict__ x_in,
                  const float* __restrict__ Qa_b, const float* __restrict__ Ka_b,
                  const float* __restrict__ Qb_b, const float* __restrict__ Kb_b,
                  int N)
{
    extern __shared__ char sh[];
    const uint32_t sb = smem_u32(sh);
    const int tid  = threadIdx.x;
    const int wid  = tid >> 5;
    const int lane = tid & 31;
    const int by   = blockIdx.y;
    const int row0 = blockIdx.x * 128;
    const float* src = by ? x_in : t_in;
    const char* wbase = (const char*)(g_wh + (size_t)(by * 3) * WELEM);

    // Prefetch first weight while converting A.
    cp_tile(sb + SM_WB, wbase);

    for (int i = tid; i < 128 * 32; i += 256) {
        int r = i >> 5, c4 = (i & 31) << 2;
        int gr = row0 + r;
        float4 v = make_float4(0.f, 0.f, 0.f, 0.f);
        if (gr < N) v = ((const float4*)(src + (size_t)gr * DDIM))[i & 31];
        uint2 h, l;
        split4h(v, h, l);
        int off = r * ROWB + c4 * 2;
        *(uint2*)(sh + SM_AHI + off) = h;
        *(uint2*)(sh + SM_ALO + off) = l;
    }
    CP_WAIT();

    const int g  = lane >> 2;
    const int tq = lane & 3;
    const int wr0 = (wid & 3) * 32;
    const int wc0 = (wid >> 2) * 64;

    #pragma unroll
    for (int w = 0; w < 3; w++) {
        if (w > 0) { cp_tile(sb + SM_WB, wbase + (size_t)w * TILEB); CP_WAIT(); }

        float acc[2][8][4] = {};

        #pragma unroll
        for (int kc = 0; kc < 8; kc++) {
            const int kb = kc * 32 + tq * 4;
            uint32_t ah[2][4], al[2][4];
            #pragma unroll
            for (int mt = 0; mt < 2; mt++) {
                int rb = (wr0 + mt * 16 + g) * ROWB + kb;
                ah[mt][0] = *(const uint32_t*)(sh + SM_AHI + rb);
                ah[mt][1] = *(const uint32_t*)(sh + SM_AHI + rb + 8 * ROWB);
                ah[mt][2] = *(const uint32_t*)(sh + SM_AHI + rb + 16);
                ah[mt][3] = *(const uint32_t*)(sh + SM_AHI + rb + 8 * ROWB + 16);
                al[mt][0] = *(const uint32_t*)(sh + SM_ALO + rb);
                al[mt][1] = *(const uint32_t*)(sh + SM_ALO + rb + 8 * ROWB);
                al[mt][2] = *(const uint32_t*)(sh + SM_ALO + rb + 16);
                al[mt][3] = *(const uint32_t*)(sh + SM_ALO + rb + 8 * ROWB + 16);
            }
            #pragma unroll
            for (int nt = 0; nt < 8; nt++) {
                int bb = (wc0 + nt * 8 + g) * ROWB + kb;
                uint32_t b0 = *(const uint32_t*)(sh + SM_WB + bb);
                uint32_t b1 = *(const uint32_t*)(sh + SM_WB + bb + 16);
                #pragma unroll
                for (int mt = 0; mt < 2; mt++) {
                    mma16816(acc[mt][nt], ah[mt], b0, b1);
                    mma16816(acc[mt][nt], al[mt], b0, b1);
                }
            }
        }

        // Epilogue: bias + fp16 pack stores.
        const float* bias = (w == 0) ? (by ? Qb_b : Qa_b)
                          : (w == 1) ? (by ? Kb_b : Ka_b) : nullptr;
        __half* out; size_t stride;
        if (w == 0)      { out = g_qpack + (by ? 128 : 0);       stride = 256; }
        else if (w == 1) { out = g_kpack + (by ? 128 : 0);       stride = 512; }
        else             { out = g_kpack + 256 + (by ? 128 : 0); stride = 512; }

        #pragma unroll
        for (int nt = 0; nt < 8; nt++) {
            const int col = wc0 + nt * 8 + 2 * tq;
            float2 bv = make_float2(0.f, 0.f);
            if (bias) bv = *(const float2*)(bias + col);
            #pragma unroll
            for (int mt = 0; mt < 2; mt++) {
                int r1 = row0 + wr0 + mt * 16 + g;
                int r2 = r1 + 8;
                if (r1 < N)
                    *(__half2*)(out + (size_t)r1 * stride + col) =
                        __floats2half2_rn(acc[mt][nt][0] + bv.x, acc[mt][nt][1] + bv.y);
                if (r2 < N)
                    *(__half2*)(out + (size_t)r2 * stride + col) =
                        __floats2half2_rn(acc[mt][nt][2] + bv.x, acc[mt][nt][3] + bv.y);
            }
        }
        __syncthreads();   // release W buffer before next weight's cp
    }
}

// ---------------------------------------------------------------------------
// CSR build: histogram -> 4-per-thread single-block scan. (Scatter is fused
// into the score pass below.)
// ---------------------------------------------------------------------------
__global__ __launch_bounds__(256)
void hist_kernel(const int* __restrict__ erow, int E)
{
    int e = blockIdx.x * blockDim.x + threadIdx.x;
    if (e < E) atomicAdd(&g_deg[erow[e]], 1);
}

__global__ __launch_bounds__(1024, 1)
void scan_kernel(int N)
{
    __shared__ int wsum[32];
    __shared__ int carry_s, ctot;
    const int tid = threadIdx.x, lane = tid & 31, wid = tid >> 5;
    if (tid == 0) carry_s = 0;
    __syncthreads();

    for (int base = 0; base < N; base += 4096) {
        int i0 = base + tid * 4;
        int d[4];
        #pragma unroll
        for (int j = 0; j < 4; j++) d[j] = (i0 + j < N) ? g_deg[i0 + j] : 0;
        int s = d[0] + d[1] + d[2] + d[3];
        int inc = s;
        #pragma unroll
        for (int o = 1; o < 32; o <<= 1) {
            int u = __shfl_up_sync(0xFFFFFFFFu, inc, o);
            if (lane >= o) inc += u;
        }
        if (lane == 31) wsum[wid] = inc;
        __syncthreads();
        if (wid == 0) {
            int t0 = wsum[lane];
            int is = t0;
            #pragma unroll
            for (int o = 1; o < 32; o <<= 1) {
                int u = __shfl_up_sync(0xFFFFFFFFu, is, o);
                if (lane >= o) is += u;
            }
            wsum[lane] = is - t0;
            if (lane == 31) ctot = is;
        }
        __syncthreads();
        int excl = carry_s + wsum[wid] + inc - s;
        #pragma unroll
        for (int j = 0; j < 4; j++) {
            if (i0 + j < N) { g_roff[i0 + j] = excl; g_cur[i0 + j] = excl; }
            excl += d[j];
        }
        __syncthreads();
        if (tid == 0) carry_s += ctot;
        __syncthreads();
    }
    if (tid == 0) g_roff[N] = carry_s;
}

// ---------------------------------------------------------------------------
// Pass A (fused scatter+score): one warp per original edge. Computes both
// exp-scores, claims the CSR slot, writes src + scores to CSR arrays.
// ---------------------------------------------------------------------------
__global__ __launch_bounds__(256)
void score_kernel(const int* __restrict__ erow, const int* __restrict__ ecol, int E)
{
    const int e    = (blockIdx.x * blockDim.x + threadIdx.x) >> 5;
    const int lane = threadIdx.x & 31;
    if (e >= E) return;

    const int r = erow[e];
    const int c = ecol[e];
    const int l4 = lane * 4;

    uint2 qa = *(const uint2*)(g_qpack + (size_t)r * 256 + l4);
    uint2 qb = *(const uint2*)(g_qpack + (size_t)r * 256 + 128 + l4);
    uint2 ka = *(const uint2*)(g_kpack + (size_t)c * 512 + l4);
    uint2 kb = *(const uint2*)(g_kpack + (size_t)c * 512 + 128 + l4);

    float2 a0 = __half22float2(*(__half2*)&qa.x), a1 = __half22float2(*(__half2*)&qa.y);
    float2 b0 = __half22float2(*(__half2*)&ka.x), b1 = __half22float2(*(__half2*)&ka.y);
    float sa = a0.x * b0.x + a0.y * b0.y + a1.x * b1.x + a1.y * b1.y;
    a0 = __half22float2(*(__half2*)&qb.x); a1 = __half22float2(*(__half2*)&qb.y);
    b0 = __half22float2(*(__half2*)&kb.x); b1 = __half22float2(*(__half2*)&kb.y);
    float sb = a0.x * b0.x + a0.y * b0.y + a1.x * b1.x + a1.y * b1.y;

    #pragma unroll
    for (int off = 16; off; off >>= 1) {
        sa += __shfl_xor_sync(0xFFFFFFFFu, sa, off);
        sb += __shfl_xor_sync(0xFFFFFFFFu, sb, off);
    }

    const float inv_sqrt_d = 0.08838834764831845f;   // 1/sqrt(128)
    if (lane == 0) {
        int slot = atomicAdd(&g_cur[r], 1);
        g_esrc[slot] = c;
        g_esc[slot] = make_float2(__expf(sa * inv_sqrt_d), __expf(sb * inv_sqrt_d));
    }
}

// ---------------------------------------------------------------------------
// Pass B: warp per node. Sequential score reads + msg gathers; loop-carried
// dependency is a single FMA. Normalized single store.
// ---------------------------------------------------------------------------
__global__ __launch_bounds__(256)
void gather_kernel(float* __restrict__ out_x, float* __restrict__ out_t, int N)
{
    const int n    = (blockIdx.x * blockDim.x + threadIdx.x) >> 5;
    const int lane = threadIdx.x & 31;
    if (n >= N) return;

    const int l4 = lane * 4;
    const int start = g_roff[n], end = g_roff[n + 1];

    float4 acct = make_float4(0.f, 0.f, 0.f, 0.f);
    float4 accx = make_float4(0.f, 0.f, 0.f, 0.f);
    float dena = 0.f, denb = 0.f;

    #pragma unroll 2
    for (int i = start; i < end; i++) {
        const int c = g_esrc[i];
        const float2 esc = g_esc[i];
        const __half* kp = g_kpack + (size_t)c * 512 + 256;
        uint2 mt = *(const uint2*)(kp + l4);
        uint2 mx = *(const uint2*)(kp + 128 + l4);

        dena += esc.x; denb += esc.y;

        float2 v0 = __half22float2(*(__half2*)&mt.x), v1 = __half22float2(*(__half2*)&mt.y);
        acct.x = fmaf(esc.x, v0.x, acct.x); acct.y = fmaf(esc.x, v0.y, acct.y);
        acct.z = fmaf(esc.x, v1.x, acct.z); acct.w = fmaf(esc.x, v1.y, acct.w);
        v0 = __half22float2(*(__half2*)&mx.x); v1 = __half22float2(*(__half2*)&mx.y);
        accx.x = fmaf(esc.y, v0.x, accx.x); accx.y = fmaf(esc.y, v0.y, accx.y);
        accx.z = fmaf(esc.y, v1.x, accx.z); accx.w = fmaf(esc.y, v1.y, accx.w);
    }

    float ra = dena > 0.f ? __fdividef(1.f, dena) : 0.f;
    float rb = denb > 0.f ? __fdividef(1.f, denb) : 0.f;
    acct.x *= ra; acct.y *= ra; acct.z *= ra; acct.w *= ra;
    accx.x *= rb; accx.y *= rb; accx.z *= rb; accx.w *= rb;

    *(float4*)(out_t + (size_t)n * DDIM + l4) = acct;
    *(float4*)(out_x + (size_t)n * DDIM + l4) = accx;
}

// ---------------------------------------------------------------------------
extern "C" void kernel_launch(void* const* d_in, const int* in_sizes, int n_in,
                              void* d_out, int out_size)
{
    const float* x    = (const float*)d_in[0];
    const float* t    = (const float*)d_in[1];
    const int*   ei   = (const int*)d_in[2];
    const float* W_x  = (const float*)d_in[3];
    const float* W_t  = (const float*)d_in[4];
    const float* Qa_w = (const float*)d_in[5];
    const float* Qa_b = (const float*)d_in[6];
    const float* Ka_w = (const float*)d_in[7];
    const float* Ka_b = (const float*)d_in[8];
    const float* Qb_w = (const float*)d_in[9];
    const float* Qb_b = (const float*)d_in[10];
    const float* Kb_w = (const float*)d_in[11];
    const float* Kb_b = (const float*)d_in[12];

    const int N = in_sizes[0] / DDIM;
    const int E = in_sizes[2] / 2;
    const int* erow = ei;         // edge_index[0] = dest
    const int* ecol = ei + E;     // edge_index[1] = src

    float* out_x = (float*)d_out;
    float* out_t = out_x + (size_t)N * DDIM;

    int* deg = nullptr;
    cudaGetSymbolAddress((void**)&deg, g_deg);
    cudaMemsetAsync(deg, 0, sizeof(int) * N, 0);

    // Weight convert (once, parallel): 0=Qa 1=Ka 2=Wt | 3=Qb 4=Kb 5=Wx
    dim3 wg(6, 8);
    wconv_kernel<<<wg, 256>>>(Qa_w, Ka_w, W_t, Qb_w, Kb_w, W_x);

    // CSR offsets
    const int eb = (E + 255) / 256;
    hist_kernel<<<eb, 256>>>(erow, E);
    scan_kernel<<<1, 1024>>>(N);

    // Projections (2 CTAs/SM)
    cudaFuncSetAttribute(gemm3_kernel,
                         cudaFuncAttributeMaxDynamicSharedMemorySize, GEMM_SMEM);
    dim3 gg((N + 127) / 128, 2);
    gemm3_kernel<<<gg, 256, GEMM_SMEM>>>(t, x, Qa_b, Ka_b, Qb_b, Kb_b, N);

    // Pass A: fused scatter+score (warp per edge)
    const int sbk = (E * 32 + 255) / 256;
    score_kernel<<<sbk, 256>>>(erow, ecol, E);

    // Pass B: per-node gather + normalize + store
    const int nb = (N * 32 + 255) / 256;
    gather_kernel<<<nb, 256>>>(out_x, out_t, N);
}